// round 16
// baseline (speedup 1.0000x reference)
#include <cuda_runtime.h>
#include <cuda_fp16.h>
#include <cstdint>

// ---------------------------------------------------------------------------
// Problem constants
// ---------------------------------------------------------------------------
#define Nn 5570            // real nodes
#define NR 5632            // padded rows / K extent (44*128)
#define JT 576             // j columns: 560 data + 1 ones (Z) + 15 pad
#define Bb 16
#define Cc 35

// Device scratch (zero-initialized; pad regions never written -> stay 0).
__device__ __half    g_Sf[(size_t)NR * NR];    // S' = exp(dot - rmax + ln1024), fp16
__device__ __half    g_Vtf[(size_t)JT * NR];   // V^T [j][m], fp16
__device__ float     g_X1[(size_t)NR * JT];    // S'@V (scaled); col 560 = Z'
__device__ unsigned  g_rowmax[NR];             // float bits of rowwise max relu(dot)

// ---------------------------------------------------------------------------
// PTX helpers (baseline ISA only; valid under virtual arch compute_103)
// ---------------------------------------------------------------------------
__device__ __forceinline__ uint32_t smem_u32(const void* p) {
    uint32_t a;
    asm("{ .reg .u64 t; cvta.to.shared.u64 t, %1; cvt.u32.u64 %0, t; }"
        : "=r"(a) : "l"(p));
    return a;
}
__device__ __forceinline__ void cp16(uint32_t saddr, const void* g) {
    asm volatile("cp.async.cg.shared.global [%0], [%1], 16;"
                 :: "r"(saddr), "l"(g) : "memory");
}
#define CP_COMMIT() asm volatile("cp.async.commit_group;" ::: "memory")
#define CP_WAIT2()  asm volatile("cp.async.wait_group 2;" ::: "memory")

__device__ __forceinline__ void ldsm4(uint32_t (&r)[4], uint32_t addr) {
    asm volatile("ldmatrix.sync.aligned.m8n8.x4.shared.b16 {%0,%1,%2,%3}, [%4];"
                 : "=r"(r[0]), "=r"(r[1]), "=r"(r[2]), "=r"(r[3]) : "r"(addr));
}
__device__ __forceinline__ void mma_f16(float* c, const uint32_t* a,
                                        const uint32_t* b) {
    asm volatile(
        "mma.sync.aligned.m16n8k16.row.col.f32.f16.f16.f32 "
        "{%0,%1,%2,%3}, {%4,%5,%6,%7}, {%8,%9}, {%0,%1,%2,%3};"
        : "+f"(c[0]), "+f"(c[1]), "+f"(c[2]), "+f"(c[3])
        : "r"(a[0]), "r"(a[1]), "r"(a[2]), "r"(a[3]), "r"(b[0]), "r"(b[1]));
}
static __device__ __forceinline__ uint32_t swz(uint32_t off) {
    return off ^ ((off >> 3) & 0x70);   // SW128 for 128B rows
}

// Fast exp via exp2 poly; valid for x in [-50, 10] (result stays normal fp32)
__device__ __forceinline__ float fast_exp(float x) {
    float t = x * 1.4426950408889634f;
    float fn = rintf(t);
    float f = t - fn;
    float p = 0.0013333558f;
    p = fmaf(p, f, 0.0096181291f);
    p = fmaf(p, f, 0.0555041087f);
    p = fmaf(p, f, 0.2402265069f);
    p = fmaf(p, f, 0.6931471806f);
    p = fmaf(p, f, 1.0f);
    return __int_as_float(__float_as_int(p) + ((int)fn << 23));
}

// ---------------------------------------------------------------------------
// Kernel 1: build V^T [j][m] fp16. Grid (44 m-tiles, 16 batches).
// ---------------------------------------------------------------------------
__global__ void prep_vt_kernel(const float* __restrict__ x) {
    __shared__ float sx[128 * Cc];
    const int m0 = blockIdx.x * 128;
    const int b  = blockIdx.y;
    const int tid = threadIdx.x;   // 256

    const int limit = min(128, Nn - m0) * Cc;
    const float* xb = x + ((size_t)b * Nn + m0) * Cc;
    for (int t = tid; t < 128 * Cc; t += 256)
        sx[t] = (t < limit) ? xb[t] : 0.0f;
    __syncthreads();

    for (int t = tid; t < Cc * 128; t += 256) {
        int c  = t >> 7;
        int mm = t & 127;
        int m  = m0 + mm;
        if (m < Nn)
            g_Vtf[(size_t)(b * Cc + c) * NR + m] = __float2half(sx[mm * Cc + c]);
    }
    if (b == 0 && tid < 128) {
        int m = m0 + tid;
        if (m < Nn) g_Vtf[(size_t)560 * NR + m] = __float2half(1.0f);
    }
}

// ---------------------------------------------------------------------------
// Kernel 2: row max of relu(e_n . e_m). Grid (11 m-tiles x 44 n-tiles).
// Positive floats: uint compare == float compare, so atomicMax on bits works.
// ---------------------------------------------------------------------------
__global__ __launch_bounds__(256) void rowmax_kernel(const float* __restrict__ e) {
    __shared__ float4 sem[512];
    const int m0 = blockIdx.x * 512;
    const int n0 = blockIdx.y * 128;
    const int tid = threadIdx.x;

    for (int t = tid; t < 512; t += 256) {
        int m = m0 + t;
        sem[t] = (m < Nn) ? ((const float4*)e)[m]
                          : make_float4(0.f, 0.f, 0.f, 0.f);
    }
    __syncthreads();

    const int row = tid >> 1, half = tid & 1;
    const int n = n0 + row;
    if (n < Nn) {
        float4 en = ((const float4*)e)[n];
        float mx = 0.0f;
        const float4* sp = sem + half * 256;
#pragma unroll 8
        for (int i = 0; i < 256; ++i) {
            float4 em = sp[i];
            float d = fmaf(en.x, em.x, fmaf(en.y, em.y,
                       fmaf(en.z, em.z, en.w * em.w)));
            mx = fmaxf(mx, d);
        }
        mx = fmaxf(mx, __shfl_xor_sync(0xffffffffu, mx, 1));
        if (half == 0)
            atomicMax(&g_rowmax[n], __float_as_uint(mx));
    }
}

// ---------------------------------------------------------------------------
// Kernel 3: S'[n,m] = exp(relu(dot) - rmax + ln1024) in fp16. Tile 128x128.
// The exp(-rmax+ln1024) row scale cancels exactly in X1/Z at the epilogue.
// ---------------------------------------------------------------------------
__global__ __launch_bounds__(256) void score_kernel(const float* __restrict__ e) {
    __shared__ float4 sem[128];
    const int n0 = blockIdx.y * 128;
    const int m0 = blockIdx.x * 128;
    const int tid = threadIdx.x;
    const int w = tid >> 5, l = tid & 31;

    if (tid < 128) {
        int m = m0 + tid;
        sem[tid] = (m < Nn) ? ((const float4*)e)[m]
                            : make_float4(0.f, 0.f, 0.f, 0.f);
    }
    __syncthreads();

    float4 em0 = sem[l * 4 + 0], em1 = sem[l * 4 + 1];
    float4 em2 = sem[l * 4 + 2], em3 = sem[l * 4 + 3];

#pragma unroll 4
    for (int rr = 0; rr < 16; ++rr) {
        int n = n0 + w * 16 + rr;
        if (n >= Nn) break;
        float4 en = ((const float4*)e)[n];   // warp-uniform -> broadcast
        float bias = 6.931471806f - __uint_as_float(g_rowmax[n]);
        float d0 = fmaf(en.x, em0.x, fmaf(en.y, em0.y, fmaf(en.z, em0.z, en.w * em0.w)));
        float d1 = fmaf(en.x, em1.x, fmaf(en.y, em1.y, fmaf(en.z, em1.z, en.w * em1.w)));
        float d2 = fmaf(en.x, em2.x, fmaf(en.y, em2.y, fmaf(en.z, em2.z, en.w * em2.w)));
        float d3 = fmaf(en.x, em3.x, fmaf(en.y, em3.y, fmaf(en.z, em3.z, en.w * em3.w)));
        float s0 = fast_exp(fmaxf(d0, 0.0f) + bias);
        float s1 = fast_exp(fmaxf(d1, 0.0f) + bias);
        float s2 = fast_exp(fmaxf(d2, 0.0f) + bias);
        float s3 = fast_exp(fmaxf(d3, 0.0f) + bias);
        size_t off = (size_t)n * NR + m0 + l * 4;
        __half2* oh = (__half2*)(g_Sf + off);
        oh[0] = __floats2half2_rn(s0, s1);
        oh[1] = __floats2half2_rn(s2, s3);
    }
}

// ---------------------------------------------------------------------------
// Kernel 4: HMMA GEMM, fp16. X1[n,j] = sum_m S'[n,m] V^T[j,m].
// CTA: 128(n) x 192(j), BK=64, 512 threads (16 warps, warp tile 32x48),
// 4-stage cp.async ring, ONE __syncthreads per iter.
//
// Pipeline safety: per iter: [A] issue loads stage it+2, [B] commit,
// [C] wait_group 2 (stage it's group, committed at iter it-2, is done),
// [D] __syncthreads (stage-it data visible to all), [E] consume stage it.
// Loads at [A] of iter it write buffer (it+2)&3, last consumed at [E] of
// iter it-2; every warp at [A](it) passed [D](it-1), which all warps reach
// only after [E](it-2). No second barrier needed.
//
// Swizzle: swz(row*128+b) = row*128 + (b ^ ((row&7)<<4)); per-ks ldmatrix
// address = row*128 + ((base ^ xorv) ^ (ks<<5)) — XOR, never add, post-swizzle.
// ---------------------------------------------------------------------------
#define OFF_A 0
#define OFF_B 16384
#define BUF_STRIDE 40960
#define NSTAGE 4
#define SMEM_REQ (NSTAGE * BUF_STRIDE + 1024)
#define NITER (NR / 64)

__global__ __launch_bounds__(512, 1) void gemm_kernel() {
    extern __shared__ char dsm[];
    uint32_t raw = smem_u32(dsm);
    const uint32_t base = raw + ((1024u - (raw & 1023u)) & 1023u);

    const int tid = threadIdx.x;
    const int lid = tid & 31;
    const int wid = tid >> 5;
    const int wm = wid & 3;            // 4 warps along n-rows (32 each)
    const int wn = wid >> 2;           // 4 warps along j-cols (48 each)
    const int n0 = blockIdx.x * 128;
    const int j0 = blockIdx.y * 192;

    const char* srcA = (const char*)g_Sf  + (size_t)n0 * (NR * 2);
    const char* srcB = (const char*)g_Vtf + (size_t)j0 * (NR * 2);

    const int lrow = tid >> 3;         // 0..63, +rr*64
    const int lq   = tid & 7;          // 16B slot in 128B row

    uint32_t arow[2], axor[2];
#pragma unroll
    for (int mt = 0; mt < 2; ++mt) {
        int row = wm * 32 + mt * 16 + (lid & 15);
        arow[mt] = row * 128;
        axor[mt] = ((lid >> 4) * 16) ^ ((row & 7) << 4);
    }
    uint32_t brow[3], bxor[3];
#pragma unroll
    for (int bp = 0; bp < 3; ++bp) {
        int row = wn * 48 + bp * 16 + ((lid >> 4) << 3) + (lid & 7);
        brow[bp] = row * 128;
        bxor[bp] = (((lid >> 3) & 1) * 16) ^ ((row & 7) << 4);
    }

    // per-thread load slots (A: 2x, B: 3x)
    const uint32_t sA0 = swz(lrow * 128 + lq * 16);
    const uint32_t sA1 = swz((lrow + 64) * 128 + lq * 16);
    const uint32_t sB2 = swz((lrow + 128) * 128 + lq * 16);
    const size_t gA0 = (size_t)lrow * (NR * 2) + lq * 16;
    const size_t gA1 = (size_t)(lrow + 64) * (NR * 2) + lq * 16;
    const size_t gB2 = (size_t)(lrow + 128) * (NR * 2) + lq * 16;

    float acc[2][6][4] = {};

#define LOAD_STAGE(IT, BUF)                                            \
    do {                                                               \
        const uint32_t so = base + (BUF) * BUF_STRIDE;                 \
        const size_t kb = (size_t)(IT) * 128;                          \
        cp16(so + OFF_A + sA0, srcA + gA0 + kb);                       \
        cp16(so + OFF_A + sA1, srcA + gA1 + kb);                       \
        cp16(so + OFF_B + sA0, srcB + gA0 + kb);                       \
        cp16(so + OFF_B + sA1, srcB + gA1 + kb);                       \
        cp16(so + OFF_B + sB2, srcB + gB2 + kb);                       \
    } while (0)

    LOAD_STAGE(0, 0); CP_COMMIT();
    LOAD_STAGE(1, 1); CP_COMMIT();

    for (int it = 0; it < NITER; ++it) {
        if (it + 2 < NITER) LOAD_STAGE(it + 2, (it + 2) & 3);
        CP_COMMIT();
        CP_WAIT2();
        __syncthreads();

        const uint32_t soff = base + (it & 3) * BUF_STRIDE;
#pragma unroll
        for (int ks = 0; ks < 4; ++ks) {
            const uint32_t kx = (uint32_t)ks << 5;
            uint32_t Af[2][4], Bf[6][2];
#pragma unroll
            for (int mt = 0; mt < 2; ++mt)
                ldsm4(Af[mt], soff + OFF_A + arow[mt] + (axor[mt] ^ kx));
#pragma unroll
            for (int bp = 0; bp < 3; ++bp) {
                uint32_t r[4];
                ldsm4(r, soff + OFF_B + brow[bp] + (bxor[bp] ^ kx));
                Bf[2 * bp][0] = r[0]; Bf[2 * bp][1] = r[1];
                Bf[2 * bp + 1][0] = r[2]; Bf[2 * bp + 1][1] = r[3];
            }
#pragma unroll
            for (int mt = 0; mt < 2; ++mt)
#pragma unroll
                for (int nt = 0; nt < 6; ++nt)
                    mma_f16(acc[mt][nt], Af[mt], Bf[nt]);
        }
    }

    // epilogue: D frag lane map: rows lid/4 and +8, cols 2*(lid%4)+{0,1}
    const int r4 = lid >> 2;
    const int c2 = (lid & 3) * 2;
#pragma unroll
    for (int mt = 0; mt < 2; ++mt) {
        int row = n0 + wm * 32 + mt * 16 + r4;
#pragma unroll
        for (int nt = 0; nt < 6; ++nt) {
            int col = j0 + wn * 48 + nt * 8 + c2;
            *(float2*)&g_X1[(size_t)row * JT + col] =
                make_float2(acc[mt][nt][0], acc[mt][nt][1]);
            *(float2*)&g_X1[(size_t)(row + 8) * JT + col] =
                make_float2(acc[mt][nt][2], acc[mt][nt][3]);
        }
    }
#undef LOAD_STAGE
}

// ---------------------------------------------------------------------------
// Kernel 5: per-node epilogue, 4 nodes per 256-thread block.
// H=0 => only R and C gates matter. xg = X1/Z (row scale cancels exactly).
// No early returns: clamped n for loads, guarded final store.
// ---------------------------------------------------------------------------
__global__ __launch_bounds__(256) void epi_kernel(
        const float* __restrict__ x,
        const float* __restrict__ e,
        const float* __restrict__ w_gate,
        const float* __restrict__ b_gate,
        const float* __restrict__ w_update,
        const float* __restrict__ b_update,
        const float* __restrict__ lin_w,
        const float* __restrict__ lin_b,
        float* __restrict__ out) {
    const int g   = threadIdx.x >> 6;           // node slot 0..3
    const int tid = threadIdx.x & 63;
    const int nraw = blockIdx.x * 4 + g;
    const int n = (nraw < Nn) ? nraw : (Nn - 1); // clamp; store guarded

    __shared__ float se[4][4];
    __shared__ float sWg[4][2][35][4];
    __shared__ float sbg[4][4];
    __shared__ float sWu[4][2][35][2];
    __shared__ float sbu[4][2];
    __shared__ float sxs[4][16][36];
    __shared__ float sxg[4][16][36];
    __shared__ float sy[4][16][2];

    if (tid < 4) se[g][tid] = e[n * 4 + tid];
    __syncthreads();

    for (int t = tid; t < 280; t += 64) {
        int o = t & 3, t2 = t >> 2;
        int i = t2 % 35, k = t2 / 35;
        float s = 0.0f;
#pragma unroll
        for (int d = 0; d < 4; ++d)
            s += se[g][d] * w_gate[(((d * 2) + k) * 37 + i) * 4 + o];
        sWg[g][k][i][o] = s;
    }
    if (tid < 4) {
        float s = 0.0f;
#pragma unroll
        for (int d = 0; d < 4; ++d) s += se[g][d] * b_gate[d * 4 + tid];
        sbg[g][tid] = s;
    }
    for (int t = tid; t < 140; t += 64) {
        int o = t & 1, t2 = t >> 1;
        int i = t2 % 35, k = t2 / 35;
        float s = 0.0f;
#pragma unroll
        for (int d = 0; d < 4; ++d)
            s += se[g][d] * w_update[(((d * 2) + k) * 37 + i) * 2 + o];
        sWu[g][k][i][o] = s;
    }
    if (tid < 2) {
        float s = 0.0f;
#pragma unroll
        for (int d = 0; d < 4; ++d) s += se[g][d] * b_update[d * 2 + tid];
        sbu[g][tid] = s;
    }

    const float invZ = 1.0f / g_X1[(size_t)n * JT + 560];
    for (int t = tid; t < 560; t += 64) {
        int b = t / 35, c = t - b * 35;
        sxs[g][b][c] = x[((size_t)b * Nn + n) * 35 + c];
        sxg[g][b][c] = g_X1[(size_t)n * JT + t] * invZ;
    }
    __syncthreads();

    if (tid < 32) {
        int b = tid >> 1, o = tid & 1;
        float gr = sbg[g][o + 2];
        float cu = sbu[g][o];
#pragma unroll
        for (int i = 0; i < 35; ++i) {
            float xs = sxs[g][b][i];
            float xg = sxg[g][b][i];
            gr += xs * sWg[g][0][i][o + 2] + xg * sWg[g][1][i][o + 2];
            cu += xs * sWu[g][0][i][o] + xg * sWu[g][1][i][o];
        }
        float R = 1.0f / (1.0f + __expf(-gr));
        float Cv = tanhf(cu);
        float h = (1.0f - R) * Cv;
        sy[g][b][o] = fmaxf(h, 0.0f) * lin_w[o];
    }
    __syncthreads();

    if (tid < 16 && nraw < Nn)
        out[tid * Nn + nraw] = sy[g][tid][0] + sy[g][tid][1] + lin_b[0];
}

// ---------------------------------------------------------------------------
extern "C" void kernel_launch(void* const* d_in, const int* in_sizes, int n_in,
                              void* d_out, int out_size) {
    const float* x        = (const float*)d_in[0];
    const float* e        = (const float*)d_in[1];
    const float* w_gate   = (const float*)d_in[2];
    const float* b_gate   = (const float*)d_in[3];
    const float* w_update = (const float*)d_in[4];
    const float* b_update = (const float*)d_in[5];
    const float* lin_w    = (const float*)d_in[6];
    const float* lin_b    = (const float*)d_in[7];
    float* out = (float*)d_out;

    (void)cudaFuncSetAttribute(gemm_kernel,
                               cudaFuncAttributeMaxDynamicSharedMemorySize,
                               SMEM_REQ);

    prep_vt_kernel<<<dim3(44, 16), 256>>>(x);
    rowmax_kernel<<<dim3(11, 44), 256>>>(e);
    score_kernel<<<dim3(44, 44), 256>>>(e);
    gemm_kernel<<<dim3(44, 3), 512, SMEM_REQ>>>();
    epi_kernel<<<(Nn + 3) / 4, 256>>>(x, e, w_gate, b_gate, w_update,
                                      b_update, lin_w, lin_b, out);
}